// round 4
// baseline (speedup 1.0000x reference)
#include <cuda_runtime.h>
#include <cstdint>

#define Bv 128
#define Tv 4096
#define DIN 64
#define Hv 512
#define DOUT 64
#define NCTA 128          // 64 layer1-CTAs + 64 layer2-CTAs, paired in 2-CTA clusters
#define NTHR 256
#define K1 576
#define K2 1024
#define K1P 580
#define K2P 1028
#define NCH1 9
#define NCH2 16
#define CHW 68            // padded chunk row stride (floats) -> conflict-free LDS
#define CHUNK_W (128 * CHW)
#define CHUNK_BYTES (CHUNK_W * 4)    // 34816
#define SMEM_WORDS (2 * CHUNK_W + 32 * K2P + 128 * 8 + 32 + 16)
#define SMEM_BYTES (SMEM_WORDS * 4)

// Persistent scratch (static __device__: the sanctioned allocation path)
__device__ float g_xT[(size_t)Tv * CHUNK_W];                 // x transposed, tf32-rounded
__device__ float g_h1[2][8][128][CHW];                       // layer1 h (tf32-rounded)
__device__ float g_h2all[(size_t)(Tv + 1) * 8 * 128 * CHW];  // h2 history; slot 0 = zeros
__device__ unsigned g_bar_count;
__device__ unsigned g_bar_epoch;                             // monotonic across replays

__device__ __forceinline__ unsigned f2tf(float x) {
    unsigned u;
    asm("cvt.rna.tf32.f32 %0, %1;" : "=r"(u) : "f"(x));
    return u;
}
__device__ __forceinline__ float sigm(float x) { return 1.0f / (1.0f + __expf(-x)); }
__device__ __forceinline__ float tanh_(float x) { return 1.0f - 2.0f / (__expf(2.0f * x) + 1.0f); }

// multicast bulk copy: one issue lands the chunk in BOTH cluster CTAs' smem,
// and delivers complete_tx to each CTA's own mbarrier at the same offset
__device__ __forceinline__ void issue_mc(unsigned sdst, const float* gsrc, unsigned mbar) {
    asm volatile(
        "cp.async.bulk.shared::cluster.global.mbarrier::complete_tx::bytes.multicast::cluster"
        " [%0], [%1], %2, [%3], %4;"
        :: "r"(sdst), "l"(gsrc), "r"((unsigned)CHUNK_BYTES), "r"(mbar),
           "h"((unsigned short)0x3) : "memory");
}
__device__ __forceinline__ void expect_tx(unsigned mbar) {
    asm volatile("mbarrier.arrive.expect_tx.shared.b64 _, [%0], %1;"
                 :: "r"(mbar), "r"((unsigned)CHUNK_BYTES) : "memory");
}
__device__ __forceinline__ void mbar_wait(unsigned mbar, unsigned parity) {
    asm volatile(
        "{\n\t.reg .pred P;\n"
        "W%=:\n\t"
        "mbarrier.try_wait.parity.acquire.cta.shared::cta.b64 P, [%0], %1, 0x989680;\n\t"
        "@!P bra W%=;\n\t}"
        :: "r"(mbar), "r"(parity) : "memory");
}
__device__ __forceinline__ void mbar_wait_clu(unsigned mbar, unsigned parity) {
    asm volatile(
        "{\n\t.reg .pred P;\n"
        "W%=:\n\t"
        "mbarrier.try_wait.parity.acquire.cluster.shared::cta.b64 P, [%0], %1, 0x989680;\n\t"
        "@!P bra W%=;\n\t}"
        :: "r"(mbar), "r"(parity) : "memory");
}
// arrive on the mbarrier at this smem offset in cluster rank 0
__device__ __forceinline__ void arrive_rank0(unsigned mbar_local) {
    asm volatile(
        "{\n\t.reg .b32 ra;\n\t"
        "mapa.shared::cluster.u32 ra, %0, 0;\n\t"
        "mbarrier.arrive.shared::cluster.b64 _, [ra];\n\t}"
        :: "r"(mbar_local) : "memory");
}

__device__ __forceinline__ void gridbar(unsigned target) {
    __syncthreads();
    if (threadIdx.x == 0) {
        __threadfence();
        unsigned old = atomicAdd(&g_bar_count, 1u);
        if (old == NCTA - 1u) {
            g_bar_count = 0u;
            __threadfence();
            *(volatile unsigned*)&g_bar_epoch = target;
        } else {
            while ((int)(*(volatile unsigned*)&g_bar_epoch - target) < 0) {}
        }
        __threadfence();
    }
    __syncthreads();
}

// One-time x transpose + tf32 round: x[b][t][64] -> xT[t][b][68-padded]
__global__ void __launch_bounds__(256)
xpose(const float* __restrict__ x) {
    const int t = blockIdx.x;
    for (int i = threadIdx.x; i < 128 * 16; i += 256) {
        int b = i >> 4, j = i & 15;
        float4 v = *(const float4*)(x + ((size_t)b * Tv + t) * 64 + j * 4);
        v.x = __uint_as_float(f2tf(v.x));
        v.y = __uint_as_float(f2tf(v.y));
        v.z = __uint_as_float(f2tf(v.z));
        v.w = __uint_as_float(f2tf(v.w));
        *(float4*)(g_xT + (size_t)t * CHUNK_W + b * CHW + j * 4) = v;
    }
}

__global__ void __launch_bounds__(NTHR, 1) __cluster_dims__(2, 1, 1)
lstm_kernel(const float* __restrict__ w_ih1, const float* __restrict__ w_hh1,
            const float* __restrict__ b_ih1, const float* __restrict__ b_hh1,
            const float* __restrict__ w_ih2, const float* __restrict__ w_hh2,
            const float* __restrict__ b_ih2, const float* __restrict__ b_hh2) {
    extern __shared__ float smf[];
    float* chunks = smf;                            // 2 x [128][CHW]
    unsigned* sw = (unsigned*)(smf + 2 * CHUNK_W);  // weights tf32 [32][K1P|K2P]
    float* sc = smf + 2 * CHUNK_W + 32 * K2P;       // c-state [128][8]
    float* sb = sc + 128 * 8;                       // fused biases [32]
    float* mbf = sb + 32;                           // 4 mbarriers
    __shared__ unsigned s_epoch0;

    const int tid = threadIdx.x;
    const bool isL2 = blockIdx.x >= 64;
    const int u0 = (blockIdx.x & 63) * 8;
    unsigned rank;
    asm("mov.u32 %0, %%cluster_ctarank;" : "=r"(rank));
    const bool leader = (rank == 0);
    const int lane = tid & 31, warp = tid >> 5;
    const int c4 = lane & 3, q = lane >> 2;
    const int r0 = warp * 16 + q, r1 = r0 + 8;
    const int KP = isL2 ? K2P : K1P;
    const int NCH = isL2 ? NCH2 : NCH1;
    const unsigned smem_base = (unsigned)__cvta_generic_to_shared(smf);
    const unsigned mb = (unsigned)__cvta_generic_to_shared(mbf);
    // full[b] = mb + b*8 ; free[b] = mb + 16 + b*8 (free lives in leader's smem)

    if (tid == 0) {
        s_epoch0 = *(volatile unsigned*)&g_bar_epoch;
        asm volatile("mbarrier.init.shared.b64 [%0], 1;" :: "r"(mb) : "memory");
        asm volatile("mbarrier.init.shared.b64 [%0], 1;" :: "r"(mb + 8) : "memory");
        asm volatile("mbarrier.init.shared.b64 [%0], 2;" :: "r"(mb + 16) : "memory");
        asm volatile("mbarrier.init.shared.b64 [%0], 2;" :: "r"(mb + 24) : "memory");
        asm volatile("fence.proxy.async.shared::cta;" ::: "memory");
    }

    // ---- stage weight slice (tf32) + fused biases ----
    if (!isL2) {
        for (int idx = tid; idx < 32 * K1; idx += NTHR) {
            int r = idx / K1, k = idx - r * K1;
            int j = (r >> 3) * Hv + u0 + (r & 7);
            float wv = (k < DIN) ? w_ih1[j * DIN + k] : w_hh1[(size_t)j * Hv + (k - DIN)];
            sw[r * K1P + k] = f2tf(wv);
        }
        if (tid < 32) {
            int j = (tid >> 3) * Hv + u0 + (tid & 7);
            sb[tid] = b_ih1[j] + b_hh1[j];
        }
    } else {
        for (int idx = tid; idx < 32 * K2; idx += NTHR) {
            int r = idx >> 10, k = idx & 1023;
            int j = (r >> 3) * Hv + u0 + (r & 7);
            float wv = (k < Hv) ? w_ih2[(size_t)j * Hv + k] : w_hh2[(size_t)j * Hv + (k - Hv)];
            sw[r * K2P + k] = f2tf(wv);
        }
        if (tid < 32) {
            int j = (tid >> 3) * Hv + u0 + (tid & 7);
            sb[tid] = b_ih2[j] + b_hh2[j];
        }
    }
    for (int i = tid; i < 128 * 8; i += NTHR) sc[i] = 0.0f;

    // ---- zero initial shared state ----
    for (int idx = blockIdx.x * NTHR + tid; idx < 2 * 8 * CHUNK_W; idx += NCTA * NTHR)
        ((float*)g_h1)[idx] = 0.0f;
    for (int idx = blockIdx.x * NTHR + tid; idx < 8 * CHUNK_W; idx += NCTA * NTHR)
        g_h2all[idx] = 0.0f;
    __syncthreads();

    // cluster handshake: peer's mbarriers inited before any remote arrive/multicast
    asm volatile("barrier.cluster.arrive.aligned;" ::: "memory");
    asm volatile("barrier.cluster.wait.aligned;" ::: "memory");
    if (tid == 0) {               // pre-arm both free barriers (2 arrivals each)
        arrive_rank0(mb + 16);
        arrive_rank0(mb + 24);
    }
    unsigned bar = s_epoch0;
    gridbar(++bar);

    unsigned ph0 = 0, ph1 = 0, f0 = 0, f1 = 0;
    const int ch = u0 >> 6, colbase = u0 & 63;

    for (int p = 0; p <= Tv; p++) {
        const bool active = isL2 ? (p >= 1) : (p < Tv);
        if (active) {
            const float* srcA;
            const float* srcB;
            if (isL2) {
                srcA = &g_h1[(p - 1) & 1][0][0][0];
                srcB = g_h2all + (size_t)(p - 1) * 8 * CHUNK_W;
            } else {
                srcA = g_xT + (size_t)p * CHUNK_W;
                srcB = &g_h1[(p - 1) & 1][0][0][0];
            }
            auto csrc = [&](int c) -> const float* {
                if (!isL2) return (c == 0) ? srcA : srcB + (size_t)(c - 1) * CHUNK_W;
                return (c < 8) ? srcA + (size_t)c * CHUNK_W : srcB + (size_t)(c - 8) * CHUNK_W;
            };

            float acc[4][4];
#pragma unroll
            for (int g = 0; g < 4; g++) {
                float b0 = sb[g * 8 + 2 * c4], b1 = sb[g * 8 + 2 * c4 + 1];
                acc[g][0] = b0; acc[g][1] = b1; acc[g][2] = b0; acc[g][3] = b1;
            }

            if (leader && tid == 0) {   // prologue: issue chunks 0,1 (gated by free)
                mbar_wait_clu(mb + 16, f0 & 1); f0++;
                issue_mc(smem_base, csrc(0), mb);
                mbar_wait_clu(mb + 24, f1 & 1); f1++;
                issue_mc(smem_base + CHUNK_BYTES, csrc(1), mb + 8);
            }

            for (int c = 0; c < NCH; c++) {
                const int bsel = c & 1;
                const unsigned fullb = mb + bsel * 8;
                if (tid == 0) expect_tx(fullb);
                mbar_wait(fullb, (bsel ? ph1 : ph0) & 1);
                if (bsel) ph1++; else ph0++;

                const float* ap = chunks + bsel * CHUNK_W + r0 * CHW + c4;
                const int kb = c * 64;
#pragma unroll
                for (int kc = 0; kc < 64; kc += 8) {
                    unsigned a0 = __float_as_uint(ap[kc]);
                    unsigned a1 = __float_as_uint(ap[kc + 8 * CHW]);
                    unsigned a2 = __float_as_uint(ap[kc + 4]);
                    unsigned a3 = __float_as_uint(ap[kc + 4 + 8 * CHW]);
#pragma unroll
                    for (int g = 0; g < 4; g++) {
                        const unsigned* bp = sw + (g * 8 + q) * KP + kb + kc + c4;
                        unsigned b0 = bp[0], b1 = bp[4];
                        asm volatile(
                            "mma.sync.aligned.m16n8k8.row.col.f32.tf32.tf32.f32 "
                            "{%0,%1,%2,%3},{%4,%5,%6,%7},{%8,%9},{%0,%1,%2,%3};"
                            : "+f"(acc[g][0]), "+f"(acc[g][1]), "+f"(acc[g][2]), "+f"(acc[g][3])
                            : "r"(a0), "r"(a1), "r"(a2), "r"(a3), "r"(b0), "r"(b1));
                    }
                }
                __syncthreads();                    // all warps done with this buffer
                if (tid == 0) arrive_rank0(mb + 16 + bsel * 8);   // buffer free (both CTAs)
                if (leader && tid == 0 && c + 2 < NCH) {
                    mbar_wait_clu(mb + 16 + bsel * 8, (bsel ? f1 : f0) & 1);
                    if (bsel) f1++; else f0++;
                    issue_mc(smem_base + bsel * CHUNK_BYTES, csrc(c + 2), fullb);
                }
            }

            // ---- epilogue: nonlinearities, c update (SMEM), tf32-rounded h store ----
            float* hout = isL2
                ? g_h2all + ((size_t)p * 8 + ch) * CHUNK_W + colbase
                : &g_h1[p & 1][ch][0][colbase];
#pragma unroll
            for (int jj = 0; jj < 2; jj++) {
                int ul = 2 * c4 + jj;
#pragma unroll
                for (int rr = 0; rr < 2; rr++) {
                    int row = rr ? r1 : r0;
                    int qi = rr * 2 + jj;
                    float iv = sigm(acc[0][qi]);
                    float fv = sigm(acc[1][qi]);
                    float gv = tanh_(acc[2][qi]);
                    float ov = sigm(acc[3][qi]);
                    float cn = fv * sc[row * 8 + ul] + iv * gv;
                    sc[row * 8 + ul] = cn;
                    hout[(size_t)row * CHW + ul] = __uint_as_float(f2tf(ov * tanh_(cn)));
                }
            }
        }
        gridbar(++bar);
    }
}

// Post-pass: out[b][t][o] = h2(t)[b] . w_out[o] + b_out[o]
__global__ void __launch_bounds__(256)
out_gemm(const float* __restrict__ w_out, const float* __restrict__ b_out,
         float* __restrict__ out) {
    __shared__ __align__(16) float As[32 * CHW];  // [k][t]
    __shared__ __align__(16) float Bs[32 * CHW];  // [k][o]
    const int b = blockIdx.y;
    const int t0 = blockIdx.x * 64;
    const int tx = threadIdx.x;
    const int to = (tx & 15) * 4;
    const int tt = (tx >> 4) * 4;
    float acc[4][4] = {};
    for (int k0 = 0; k0 < Hv; k0 += 32) {
        for (int i = tx; i < 512; i += 256) {
            int row = i >> 3, kq = (i & 7) * 4;
            const float* src = g_h2all + ((size_t)(t0 + row + 1) * 8 + (k0 >> 6)) * CHUNK_W
                             + (size_t)b * CHW + (k0 & 63) + kq;
            float4 v = *(const float4*)src;
            As[(kq + 0) * CHW + row] = v.x;
            As[(kq + 1) * CHW + row] = v.y;
            As[(kq + 2) * CHW + row] = v.z;
            As[(kq + 3) * CHW + row] = v.w;
        }
        for (int i = tx; i < 512; i += 256) {
            int o = i >> 3, kq = (i & 7) * 4;
            float4 v = *(const float4*)(w_out + (size_t)o * Hv + k0 + kq);
            Bs[(kq + 0) * CHW + o] = v.x;
            Bs[(kq + 1) * CHW + o] = v.y;
            Bs[(kq + 2) * CHW + o] = v.z;
            Bs[(kq + 3) * CHW + o] = v.w;
        }
        __syncthreads();
#pragma unroll
        for (int k = 0; k < 32; k++) {
            float4 a = *(const float4*)(As + k * CHW + tt);
            float4 w = *(const float4*)(Bs + k * CHW + to);
            acc[0][0] = fmaf(a.x, w.x, acc[0][0]); acc[0][1] = fmaf(a.x, w.y, acc[0][1]);
            acc[0][2] = fmaf(a.x, w.z, acc[0][2]); acc[0][3] = fmaf(a.x, w.w, acc[0][3]);
            acc[1][0] = fmaf(a.y, w.x, acc[1][0]); acc[1][1] = fmaf(a.y, w.y, acc[1][1]);
            acc[1][2] = fmaf(a.y, w.z, acc[1][2]); acc[1][3] = fmaf(a.y, w.w, acc[1][3]);
            acc[2][0] = fmaf(a.z, w.x, acc[2][0]); acc[2][1] = fmaf(a.z, w.y, acc[2][1]);
            acc[2][2] = fmaf(a.z, w.z, acc[2][2]); acc[2][3] = fmaf(a.z, w.w, acc[2][3]);
            acc[3][0] = fmaf(a.w, w.x, acc[3][0]); acc[3][1] = fmaf(a.w, w.y, acc[3][1]);
            acc[3][2] = fmaf(a.w, w.z, acc[3][2]); acc[3][3] = fmaf(a.w, w.w, acc[3][3]);
        }
        __syncthreads();
    }
    float bo0 = b_out[to + 0], bo1 = b_out[to + 1], bo2 = b_out[to + 2], bo3 = b_out[to + 3];
#pragma unroll
    for (int i = 0; i < 4; i++) {
        float4 r;
        r.x = acc[i][0] + bo0; r.y = acc[i][1] + bo1;
        r.z = acc[i][2] + bo2; r.w = acc[i][3] + bo3;
        *(float4*)(out + ((size_t)b * Tv + t0 + tt + i) * DOUT + to) = r;
    }
}

extern "C" void kernel_launch(void* const* d_in, const int* in_sizes, int n_in,
                              void* d_out, int out_size) {
    (void)in_sizes; (void)n_in; (void)out_size;
    const float* x     = (const float*)d_in[0];
    const float* w_ih1 = (const float*)d_in[1];
    const float* w_hh1 = (const float*)d_in[2];
    const float* b_ih1 = (const float*)d_in[3];
    const float* b_hh1 = (const float*)d_in[4];
    const float* w_ih2 = (const float*)d_in[5];
    const float* w_hh2 = (const float*)d_in[6];
    const float* b_ih2 = (const float*)d_in[7];
    const float* b_hh2 = (const float*)d_in[8];
    const float* w_out = (const float*)d_in[9];
    const float* b_out = (const float*)d_in[10];

    xpose<<<Tv, 256>>>(x);
    cudaFuncSetAttribute(lstm_kernel, cudaFuncAttributeMaxDynamicSharedMemorySize, SMEM_BYTES);
    lstm_kernel<<<NCTA, NTHR, SMEM_BYTES>>>(w_ih1, w_hh1, b_ih1, b_hh1,
                                            w_ih2, w_hh2, b_ih2, b_hh2);
    out_gemm<<<dim3(Tv / 64, Bv), 256>>>(w_out, b_out, (float*)d_out);
}

// round 5
// speedup vs baseline: 1.6892x; 1.6892x over previous
#include <cuda_runtime.h>
#include <cuda_fp16.h>
#include <cstdint>

#define Bv 128
#define Tv 4096
#define DIN 64
#define Hv 512
#define DOUT 64
#define NCTA 128
#define NTHR 256
#define K1 576
#define K2 1024
#define K1PH 584            // weight row stride (halfs): 584/2=292 words, mod32=4 -> conflict-free
#define K2PH 1032           // 516 words mod32=4 -> conflict-free
#define NCH1 9
#define NCH2 16
#define NBUF 4
#define GW 72               // chunk row stride (halfs): 36 words/row, 4q+c4 distinct -> conflict-free
#define CHUNK_W (128 * GW)  // halfs per chunk
#define CHUNK_BYTES (CHUNK_W * 2)   // 18432
#define OW 68               // out_gemm smem stride (floats)
#define SMEM_BYTES (NBUF * CHUNK_BYTES + 32 * K2PH * 2 + 128 * 8 * 4 + 32 * 4 + 64)

// Persistent scratch (static __device__: the sanctioned allocation path)
__device__ __half g_xT[(size_t)Tv * CHUNK_W];                 // x transposed, fp16
__device__ __half g_h1[2][8][128][GW];                        // layer1 h (fp16), chunk-major
__device__ __half g_h2all[(size_t)(Tv + 1) * 8 * CHUNK_W];    // h2 history; slot 0 = zeros
__device__ unsigned g_bar_count;
__device__ unsigned g_bar_epoch;                              // monotonic across replays

__device__ __forceinline__ float sigm(float x) { return 1.0f / (1.0f + __expf(-x)); }
__device__ __forceinline__ float tanh_(float x) { return 1.0f - 2.0f / (__expf(2.0f * x) + 1.0f); }

__device__ __forceinline__ void issue_chunk(unsigned sdst, const void* gsrc, unsigned mbar) {
    asm volatile("mbarrier.arrive.expect_tx.shared.b64 _, [%0], %1;"
                 :: "r"(mbar), "r"((unsigned)CHUNK_BYTES) : "memory");
    asm volatile("cp.async.bulk.shared::cta.global.mbarrier::complete_tx::bytes [%0], [%1], %2, [%3];"
                 :: "r"(sdst), "l"(gsrc), "r"((unsigned)CHUNK_BYTES), "r"(mbar) : "memory");
}
__device__ __forceinline__ void mbar_wait(unsigned mbar, unsigned parity) {
    asm volatile(
        "{\n\t.reg .pred P;\n"
        "W%=:\n\t"
        "mbarrier.try_wait.parity.acquire.cta.shared::cta.b64 P, [%0], %1, 0x989680;\n\t"
        "@!P bra W%=;\n\t}"
        :: "r"(mbar), "r"(parity) : "memory");
}

__device__ __forceinline__ void gridbar(unsigned target) {
    __syncthreads();
    if (threadIdx.x == 0) {
        __threadfence();
        unsigned old = atomicAdd(&g_bar_count, 1u);
        if (old == NCTA - 1u) {
            g_bar_count = 0u;
            __threadfence();
            *(volatile unsigned*)&g_bar_epoch = target;
        } else {
            while ((int)(*(volatile unsigned*)&g_bar_epoch - target) < 0) {}
        }
        __threadfence();
    }
    __syncthreads();
}

// One-time x transpose + fp16 round: x[b][t][64] -> xT[t][b][72-padded]
__global__ void __launch_bounds__(256)
xpose(const float* __restrict__ x) {
    const int t = blockIdx.x;
    for (int i = threadIdx.x; i < 128 * 16; i += 256) {
        int b = i >> 4, j = i & 15;
        float4 v = *(const float4*)(x + ((size_t)b * Tv + t) * 64 + j * 4);
        __half2* dst = (__half2*)(g_xT + (size_t)t * CHUNK_W + b * GW + j * 4);
        dst[0] = __floats2half2_rn(v.x, v.y);
        dst[1] = __floats2half2_rn(v.z, v.w);
    }
}

__global__ void __launch_bounds__(NTHR, 1)
lstm_kernel(const float* __restrict__ w_ih1, const float* __restrict__ w_hh1,
            const float* __restrict__ b_ih1, const float* __restrict__ b_hh1,
            const float* __restrict__ w_ih2, const float* __restrict__ w_hh2,
            const float* __restrict__ b_ih2, const float* __restrict__ b_hh2) {
    extern __shared__ __half smh[];
    __half* chunks = smh;                            // NBUF x [128][GW]
    __half* swh = smh + NBUF * CHUNK_W;              // weights fp16 [32][K1PH|K2PH]
    float* sc = (float*)(swh + 32 * K2PH);           // c-state [128][8]
    float* sb = sc + 128 * 8;                        // fused biases [32]
    float* mbf = sb + 32;                            // 4 mbarriers
    __shared__ unsigned s_epoch0;

    const int tid = threadIdx.x;
    const bool isL2 = blockIdx.x >= 64;
    const int u0 = (blockIdx.x & 63) * 8;
    const int lane = tid & 31, warp = tid >> 5;
    const int c4 = lane & 3, q = lane >> 2;
    const int r0 = warp * 16 + q, r1 = r0 + 8;
    const int KPH = isL2 ? K2PH : K1PH;
    const int NCH = isL2 ? NCH2 : NCH1;
    const unsigned smem_base = (unsigned)__cvta_generic_to_shared(smh);
    const unsigned mb = (unsigned)__cvta_generic_to_shared(mbf);

    if (tid == 0) {
        s_epoch0 = *(volatile unsigned*)&g_bar_epoch;
#pragma unroll
        for (int b = 0; b < NBUF; b++)
            asm volatile("mbarrier.init.shared.b64 [%0], 1;" :: "r"(mb + b * 8) : "memory");
        asm volatile("fence.proxy.async.shared::cta;" ::: "memory");
    }

    // ---- stage weight slice (fp16) + fused biases ----
    if (!isL2) {
        for (int idx = tid; idx < 32 * K1; idx += NTHR) {
            int r = idx / K1, k = idx - r * K1;
            int j = (r >> 3) * Hv + u0 + (r & 7);
            float wv = (k < DIN) ? w_ih1[j * DIN + k] : w_hh1[(size_t)j * Hv + (k - DIN)];
            swh[r * K1PH + k] = __float2half_rn(wv);
        }
        if (tid < 32) {
            int j = (tid >> 3) * Hv + u0 + (tid & 7);
            sb[tid] = b_ih1[j] + b_hh1[j];
        }
    } else {
        for (int idx = tid; idx < 32 * K2; idx += NTHR) {
            int r = idx >> 10, k = idx & 1023;
            int j = (r >> 3) * Hv + u0 + (r & 7);
            float wv = (k < Hv) ? w_ih2[(size_t)j * Hv + k] : w_hh2[(size_t)j * Hv + (k - Hv)];
            swh[r * K2PH + k] = __float2half_rn(wv);
        }
        if (tid < 32) {
            int j = (tid >> 3) * Hv + u0 + (tid & 7);
            sb[tid] = b_ih2[j] + b_hh2[j];
        }
    }
    for (int i = tid; i < 128 * 8; i += NTHR) sc[i] = 0.0f;

    // ---- zero initial shared state (h1 slot 1, h2 slot 0), as 4B words ----
    {
        unsigned* z1 = (unsigned*)&g_h1[1][0][0][0];
        unsigned* z2 = (unsigned*)g_h2all;
        const int nw = 8 * CHUNK_W / 2;
        for (int idx = blockIdx.x * NTHR + tid; idx < nw; idx += NCTA * NTHR) {
            z1[idx] = 0u;
            z2[idx] = 0u;
        }
    }
    __syncthreads();
    unsigned bar = s_epoch0;
    gridbar(++bar);

    unsigned phbits = 0;
    const int ch = u0 >> 6, colbase = u0 & 63;

    for (int p = 0; p <= Tv; p++) {
        const bool active = isL2 ? (p >= 1) : (p < Tv);
        if (active) {
            const __half* srcA;
            const __half* srcB;
            if (isL2) {
                srcA = &g_h1[(p - 1) & 1][0][0][0];
                srcB = g_h2all + (size_t)(p - 1) * 8 * CHUNK_W;
            } else {
                srcA = g_xT + (size_t)p * CHUNK_W;
                srcB = &g_h1[(p - 1) & 1][0][0][0];
            }
            auto csrc = [&](int c) -> const __half* {
                if (!isL2) return (c == 0) ? srcA : srcB + (size_t)(c - 1) * CHUNK_W;
                return (c < 8) ? srcA + (size_t)c * CHUNK_W : srcB + (size_t)(c - 8) * CHUNK_W;
            };

            float acc[4][4];
#pragma unroll
            for (int g = 0; g < 4; g++) {
                float b0 = sb[g * 8 + 2 * c4], b1 = sb[g * 8 + 2 * c4 + 1];
                acc[g][0] = b0; acc[g][1] = b1; acc[g][2] = b0; acc[g][3] = b1;
            }

            if (tid == 0) {
                const int ni = (NCH < NBUF) ? NCH : NBUF;
                for (int c = 0; c < ni; c++)
                    issue_chunk(smem_base + c * CHUNK_BYTES, csrc(c), mb + c * 8);
            }

            for (int c = 0; c < NCH; c++) {
                const int bsel = c & 3;
                mbar_wait(mb + bsel * 8, (phbits >> bsel) & 1u);
                phbits ^= (1u << bsel);

                const __half* ar0 = chunks + bsel * CHUNK_W + r0 * GW + 2 * c4;
                const __half* ar1 = chunks + bsel * CHUNK_W + r1 * GW + 2 * c4;
                const int kb = c * 64;
#pragma unroll
                for (int kc = 0; kc < 64; kc += 16) {
                    unsigned a0 = *(const unsigned*)(ar0 + kc);
                    unsigned a1 = *(const unsigned*)(ar1 + kc);
                    unsigned a2 = *(const unsigned*)(ar0 + kc + 8);
                    unsigned a3 = *(const unsigned*)(ar1 + kc + 8);
#pragma unroll
                    for (int g = 0; g < 4; g++) {
                        const __half* bp = swh + (g * 8 + q) * KPH + kb + kc + 2 * c4;
                        unsigned b0 = *(const unsigned*)bp;
                        unsigned b1 = *(const unsigned*)(bp + 8);
                        asm volatile(
                            "mma.sync.aligned.m16n8k16.row.col.f32.f16.f16.f32 "
                            "{%0,%1,%2,%3},{%4,%5,%6,%7},{%8,%9},{%0,%1,%2,%3};"
                            : "+f"(acc[g][0]), "+f"(acc[g][1]), "+f"(acc[g][2]), "+f"(acc[g][3])
                            : "r"(a0), "r"(a1), "r"(a2), "r"(a3), "r"(b0), "r"(b1));
                    }
                }
                __syncthreads();                    // all warps done with this buffer
                if (tid == 0 && c + NBUF < NCH)
                    issue_chunk(smem_base + bsel * CHUNK_BYTES, csrc(c + NBUF), mb + bsel * 8);
            }

            // ---- epilogue: nonlinearities, c update (SMEM), fp16 h store ----
            __half* hout = isL2
                ? g_h2all + ((size_t)p * 8 + ch) * CHUNK_W + colbase
                : &g_h1[p & 1][ch][0][colbase];
#pragma unroll
            for (int jj = 0; jj < 2; jj++) {
                int ul = 2 * c4 + jj;
#pragma unroll
                for (int rr = 0; rr < 2; rr++) {
                    int row = rr ? r1 : r0;
                    int qi = rr * 2 + jj;
                    float iv = sigm(acc[0][qi]);
                    float fv = sigm(acc[1][qi]);
                    float gv = tanh_(acc[2][qi]);
                    float ov = sigm(acc[3][qi]);
                    float cn = fv * sc[row * 8 + ul] + iv * gv;
                    sc[row * 8 + ul] = cn;
                    hout[(size_t)row * GW + ul] = __float2half_rn(ov * tanh_(cn));
                }
            }
        }
        gridbar(++bar);
    }
}

// Post-pass: out[b][t][o] = h2(t)[b] . w_out[o] + b_out[o]
__global__ void __launch_bounds__(256)
out_gemm(const float* __restrict__ w_out, const float* __restrict__ b_out,
         float* __restrict__ out) {
    __shared__ __align__(16) float As[32 * OW];  // [k][t]
    __shared__ __align__(16) float Bs[32 * OW];  // [k][o]
    const int b = blockIdx.y;
    const int t0 = blockIdx.x * 64;
    const int tx = threadIdx.x;
    const int to = (tx & 15) * 4;
    const int tt = (tx >> 4) * 4;
    float acc[4][4] = {};
    for (int k0 = 0; k0 < Hv; k0 += 32) {
        for (int i = tx; i < 512; i += 256) {
            int row = i >> 3, kq = (i & 7) * 4;
            const __half* src = g_h2all + ((size_t)(t0 + row + 1) * 8 + (k0 >> 6)) * CHUNK_W
                              + (size_t)b * GW + (k0 & 63) + kq;
            float2 f0 = __half22float2(*(const __half2*)(src));
            float2 f1 = __half22float2(*(const __half2*)(src + 2));
            As[(kq + 0) * OW + row] = f0.x;
            As[(kq + 1) * OW + row] = f0.y;
            As[(kq + 2) * OW + row] = f1.x;
            As[(kq + 3) * OW + row] = f1.y;
        }
        for (int i = tx; i < 512; i += 256) {
            int o = i >> 3, kq = (i & 7) * 4;
            float4 v = *(const float4*)(w_out + (size_t)o * Hv + k0 + kq);
            Bs[(kq + 0) * OW + o] = v.x;
            Bs[(kq + 1) * OW + o] = v.y;
            Bs[(kq + 2) * OW + o] = v.z;
            Bs[(kq + 3) * OW + o] = v.w;
        }
        __syncthreads();
#pragma unroll
        for (int k = 0; k < 32; k++) {
            float4 a = *(const float4*)(As + k * OW + tt);
            float4 w = *(const float4*)(Bs + k * OW + to);
            acc[0][0] = fmaf(a.x, w.x, acc[0][0]); acc[0][1] = fmaf(a.x, w.y, acc[0][1]);
            acc[0][2] = fmaf(a.x, w.z, acc[0][2]); acc[0][3] = fmaf(a.x, w.w, acc[0][3]);
            acc[1][0] = fmaf(a.y, w.x, acc[1][0]); acc[1][1] = fmaf(a.y, w.y, acc[1][1]);
            acc[1][2] = fmaf(a.y, w.z, acc[1][2]); acc[1][3] = fmaf(a.y, w.w, acc[1][3]);
            acc[2][0] = fmaf(a.z, w.x, acc[2][0]); acc[2][1] = fmaf(a.z, w.y, acc[2][1]);
            acc[2][2] = fmaf(a.z, w.z, acc[2][2]); acc[2][3] = fmaf(a.z, w.w, acc[2][3]);
            acc[3][0] = fmaf(a.w, w.x, acc[3][0]); acc[3][1] = fmaf(a.w, w.y, acc[3][1]);
            acc[3][2] = fmaf(a.w, w.z, acc[3][2]); acc[3][3] = fmaf(a.w, w.w, acc[3][3]);
        }
        __syncthreads();
    }
    float bo0 = b_out[to + 0], bo1 = b_out[to + 1], bo2 = b_out[to + 2], bo3 = b_out[to + 3];
#pragma unroll
    for (int i = 0; i < 4; i++) {
        float4 r;
        r.x = acc[i][0] + bo0; r.y = acc[i][1] + bo1;
        r.z = acc[i][2] + bo2; r.w = acc[i][3] + bo3;
        *(float4*)(out + ((size_t)b * Tv + t0 + tt + i) * DOUT + to) = r;
    }
}

extern "C" void kernel_launch(void* const* d_in, const int* in_sizes, int n_in,
                              void* d_out, int out_size) {
    (void)in_sizes; (void)n_in; (void)out_size;
    const float* x     = (const float*)d_in[0];
    const float* w_ih1 = (const float*)d_in[1];
    const float* w_hh1 = (const float*)d_in[2];
    const float* b_ih1 = (const float*)d_in[3];
    const float* b_hh1 = (const float*)d_in[4];
    const float* w_ih2 = (const float*)d_in[5];
    const float* w_hh2 = (const float*)d_in[6];
    const float* b_ih2 = (const float*)d_in[7];
    const float* b_hh2 = (const float*)d_in[8];
    const float* w_out = (const float*)d_in[9];
    const float* b_out = (const float*)d_in[10];

    xpose<<<Tv, 256>>>(x);
    cudaFuncSetAttribute(lstm_kernel, cudaFuncAttributeMaxDynamicSharedMemorySize, SMEM_BYTES);
    lstm_kernel<<<NCTA, NTHR, SMEM_BYTES>>>(w_ih1, w_hh1, b_ih1, b_hh1,
                                            w_ih2, w_hh2, b_ih2, b_hh2);
    out_gemm<<<dim3(Tv / 64, Bv), 256>>>(w_out, b_out, (float*)d_out);
}